// round 3
// baseline (speedup 1.0000x reference)
#include <cuda_runtime.h>
#include <cstdint>
#include <cstddef>

// Problem constants (fixed by the dataset)
#define NQ   2048
#define NS   65536
#define FD   512
#define KNN  16

// Tiling
#define BQ   128
#define BS   128
#define KC   16
#define NCHUNK (FD / KC)        // 32
#define SPLITS 9
#define SPS   7296              // 57 * 128 support per split (last split clipped)
#define TILES_PER_SPLIT 57
#define SD_STRIDE (BS + 1)      // padded dist-tile row to avoid bank conflicts

typedef unsigned long long ull;

// -------- scratch (static device globals: no allocation allowed) ----------
__device__ float g_q2[NQ];
__device__ float g_s2[NS];
__device__ float g_pd[NQ * SPLITS * 32];
__device__ int   g_pi[NQ * SPLITS * 32];

// -------- packed fp32x2 helpers (Blackwell FFMA2 path) --------------------
__device__ __forceinline__ ull rep2(float x) {
    ull r; asm("mov.b64 %0, {%1, %1};" : "=l"(r) : "f"(x)); return r;
}
__device__ __forceinline__ void fma2(ull &acc, ull a, ull b) {
    asm("fma.rn.f32x2 %0, %1, %2, %0;" : "+l"(acc) : "l"(a), "l"(b));
}
__device__ __forceinline__ void unpack2(ull v, float &lo, float &hi) {
    asm("mov.b64 {%0, %1}, %2;" : "=f"(lo), "=f"(hi) : "l"(v));
}

// -------- top-k helpers ----------------------------------------------------
__device__ __forceinline__ bool better(float d1, int i1, float d2, int i2) {
    return d1 < d2 || (d1 == d2 && i1 < i2);
}

// Ripple-insert into a sorted (ascending by (dist, idx)) register list.
// Caller guarantees the candidate beats the current worst entry.
__device__ __forceinline__ void insert16(float (&kd)[KNN], int (&ki)[KNN],
                                         float d, int i) {
    float cd = d; int ci = i;
#pragma unroll
    for (int j = 0; j < KNN; ++j) {
        bool b = better(cd, ci, kd[j], ki[j]);
        float td = kd[j]; int ti = ki[j];
        if (b) { kd[j] = cd; ki[j] = ci; cd = td; ci = ti; }
    }
}

// -------- kernel 0: row norms ---------------------------------------------
// one warp per row of 512 floats
__global__ void knn_norms_kernel(const float* __restrict__ x, int nrows, int which) {
    int w    = (blockIdx.x * blockDim.x + threadIdx.x) >> 5;
    int lane = threadIdx.x & 31;
    if (w >= nrows) return;
    const float4* row = reinterpret_cast<const float4*>(x + (size_t)w * FD);
    float s = 0.f;
#pragma unroll
    for (int i = 0; i < FD / 4 / 32; ++i) {    // 4 iterations
        float4 v = row[lane + i * 32];
        s += v.x * v.x + v.y * v.y + v.z * v.z + v.w * v.w;
    }
#pragma unroll
    for (int o = 16; o > 0; o >>= 1) s += __shfl_xor_sync(0xffffffffu, s, o);
    if (lane == 0) {
        if (which) g_s2[w] = s; else g_q2[w] = s;
    }
}

// -------- kernel 1: fused distance GEMM + per-split top-16 ----------------
// grid (NQ/BQ = 16, SPLITS = 9), 256 threads
__global__ __launch_bounds__(256, 1)
void knn_main_kernel(const float* __restrict__ Q, const float* __restrict__ S) {
    extern __shared__ float smem[];
    float* smA = smem;                       // 2 * KC * BQ = 4096 floats
    float* smB = smA + 2 * KC * BQ;          // 4096 floats
    float* sd  = smB + 2 * KC * BS;          // BQ * (BS+1) = 16512 floats
    float* q2s = sd + BQ * SD_STRIDE;        // 128
    float* s2s = q2s + BQ;                   // 128

    const int tid = threadIdx.x;
    const int tx = tid & 15, ty = tid >> 4;
    const int qb = blockIdx.x, sb = blockIdx.y;
    const int q0 = qb * BQ;
    const int sBase = sb * SPS;

    if (tid < BQ) q2s[tid] = g_q2[q0 + tid];

    float kd[KNN]; int ki[KNN];
#pragma unroll
    for (int j = 0; j < KNN; ++j) { kd[j] = __int_as_float(0x7f800000); ki[j] = 0x7fffffff; }

    const int qrow = tid >> 1;     // top-k: 2 threads per query row
    const int hh   = tid & 1;

    for (int t = 0; t < TILES_PER_SPLIT; ++t) {
        const int s0 = sBase + t * BS;
        if (s0 >= NS) break;                 // clip last split (no partial tiles)
        if (tid < BS) s2s[tid] = g_s2[s0 + tid];

        ull acc[8][4];
#pragma unroll
        for (int s = 0; s < 8; ++s)
#pragma unroll
            for (int p = 0; p < 4; ++p) acc[s][p] = 0ull;

        // ---- stage K-chunk 0 into smem buffer 0 (transposed: [k][row]) ----
#pragma unroll
        for (int i = 0; i < 2; ++i) {
            int idx = tid + i * 256;
            int row = idx >> 2, kk = (idx & 3) << 2;
            float4 va = *reinterpret_cast<const float4*>(Q + (size_t)(q0 + row) * FD + kk);
            float* da = smA + kk * BQ + row;
            da[0] = va.x; da[BQ] = va.y; da[2 * BQ] = va.z; da[3 * BQ] = va.w;
            float4 vb = *reinterpret_cast<const float4*>(S + (size_t)(s0 + row) * FD + kk);
            float* db = smB + kk * BS + row;
            db[0] = vb.x; db[BS] = vb.y; db[2 * BS] = vb.z; db[3 * BS] = vb.w;
        }
        __syncthreads();

        // ---- K loop: double-buffered, FFMA2 inner product ----
        for (int c = 0; c < NCHUNK; ++c) {
            const int cur = c & 1, nxt = cur ^ 1;
            float4 pa[2], pb[2];
            const bool has_next = (c + 1 < NCHUNK);
            if (has_next) {
                const int cc = (c + 1) * KC;
#pragma unroll
                for (int i = 0; i < 2; ++i) {
                    int idx = tid + i * 256;
                    int row = idx >> 2, kk = (idx & 3) << 2;
                    pa[i] = *reinterpret_cast<const float4*>(Q + (size_t)(q0 + row) * FD + cc + kk);
                    pb[i] = *reinterpret_cast<const float4*>(S + (size_t)(s0 + row) * FD + cc + kk);
                }
            }
            const float* Ab = smA + cur * (KC * BQ);
            const float* Bb = smB + cur * (KC * BS);
#pragma unroll
            for (int k = 0; k < KC; ++k) {
                // a: 4 query pairs (packed f32x2), broadcast across tx
                const ull* ap = reinterpret_cast<const ull*>(Ab + k * BQ + ty * 8);
                ull a0 = ap[0], a1 = ap[1], a2 = ap[2], a3 = ap[3];
                const float4* bp = reinterpret_cast<const float4*>(Bb + k * BS + tx * 8);
                float4 b0 = bp[0], b1 = bp[1];
                float bv[8] = {b0.x, b0.y, b0.z, b0.w, b1.x, b1.y, b1.z, b1.w};
#pragma unroll
                for (int s = 0; s < 8; ++s) {
                    ull bb = rep2(bv[s]);
                    fma2(acc[s][0], a0, bb);
                    fma2(acc[s][1], a1, bb);
                    fma2(acc[s][2], a2, bb);
                    fma2(acc[s][3], a3, bb);
                }
            }
            if (has_next) {
#pragma unroll
                for (int i = 0; i < 2; ++i) {
                    int idx = tid + i * 256;
                    int row = idx >> 2, kk = (idx & 3) << 2;
                    float* da = smA + nxt * (KC * BQ) + kk * BQ + row;
                    da[0] = pa[i].x; da[BQ] = pa[i].y; da[2 * BQ] = pa[i].z; da[3 * BQ] = pa[i].w;
                    float* db = smB + nxt * (KC * BS) + kk * BS + row;
                    db[0] = pb[i].x; db[BS] = pb[i].y; db[2 * BS] = pb[i].z; db[3 * BS] = pb[i].w;
                }
            }
            __syncthreads();
        }

        // ---- spill dot products to padded smem tile ----
#pragma unroll
        for (int p = 0; p < 4; ++p) {
            int r0 = ty * 8 + 2 * p;
#pragma unroll
            for (int s = 0; s < 8; ++s) {
                float lo, hi; unpack2(acc[s][p], lo, hi);
                sd[r0 * SD_STRIDE + tx * 8 + s] = lo;
                sd[(r0 + 1) * SD_STRIDE + tx * 8 + s] = hi;
            }
        }
        __syncthreads();

        // ---- top-k scan: 2 threads per query, 64 candidates each ----
        {
            const float  q2v  = q2s[qrow];
            const float* drow = sd + qrow * SD_STRIDE + hh * 64;
            const float* s2p  = s2s + hh * 64;
#pragma unroll 8
            for (int j = 0; j < 64; ++j) {
                float d2 = fmaxf(q2v + s2p[j] - 2.f * drow[j], 1e-12f);
                int idx = s0 + hh * 64 + j;
                if (better(d2, idx, kd[KNN - 1], ki[KNN - 1])) insert16(kd, ki, d2, idx);
            }
        }
        __syncthreads();   // s2s is rewritten at the top of the next tile
    }

    // ---- emit per-(query, split) partial lists: 2 halves of 16 ----
    {
        size_t base = ((size_t)(q0 + qrow) * SPLITS + sb) * 32 + (size_t)hh * 16;
#pragma unroll
        for (int r = 0; r < KNN; ++r) { g_pd[base + r] = kd[r]; g_pi[base + r] = ki[r]; }
    }
}

// -------- kernel 2: merge partials, final sorted top-16 + weights ---------
__global__ void knn_merge_kernel(float* __restrict__ out) {
    int q = blockIdx.x * blockDim.x + threadIdx.x;
    if (q >= NQ) return;
    float kd[KNN]; int ki[KNN];
#pragma unroll
    for (int j = 0; j < KNN; ++j) { kd[j] = __int_as_float(0x7f800000); ki[j] = 0x7fffffff; }
    const float* pd = g_pd + (size_t)q * SPLITS * 32;
    const int*   pi = g_pi + (size_t)q * SPLITS * 32;
    for (int c = 0; c < SPLITS * 32; ++c) {
        float d = pd[c]; int id = pi[c];
        if (better(d, id, kd[KNN - 1], ki[KNN - 1])) insert16(kd, ki, d, id);
    }
    float sim[KNN]; float sum = 0.f;
#pragma unroll
    for (int r = 0; r < KNN; ++r) {
        float dist = sqrtf(kd[r]);          // kd already clamped at 1e-12
        sim[r] = 1.f / (dist + 1e-6f);
        sum += sim[r];
    }
    float inv = 1.f / sum;
#pragma unroll
    for (int r = 0; r < KNN; ++r) {
        out[q * KNN + r] = (float)ki[r];                    // indices (exact in fp32)
        out[NQ * KNN + q * KNN + r] = sim[r] * inv;         // weights
    }
}

// -------- launch ----------------------------------------------------------
extern "C" void kernel_launch(void* const* d_in, const int* in_sizes, int n_in,
                              void* d_out, int out_size) {
    (void)in_sizes; (void)n_in; (void)out_size;
    const float* Q = (const float*)d_in[0];
    const float* S = (const float*)d_in[1];
    float* out = (float*)d_out;

    const int smem_bytes = (2 * KC * BQ + 2 * KC * BS + BQ * SD_STRIDE + BQ + BS) * 4; // 99840
    cudaFuncSetAttribute(knn_main_kernel,
                         cudaFuncAttributeMaxDynamicSharedMemorySize, smem_bytes);

    knn_norms_kernel<<<(NQ * 32) / 256, 256>>>(Q, NQ, 0);
    knn_norms_kernel<<<(NS * 32) / 256, 256>>>(S, NS, 1);

    dim3 grid(NQ / BQ, SPLITS);
    knn_main_kernel<<<grid, 256, smem_bytes>>>(Q, S);

    knn_merge_kernel<<<NQ / 256, 256>>>(out);
}

// round 12
// speedup vs baseline: 3.3812x; 3.3812x over previous
#include <cuda_runtime.h>
#include <cstdint>
#include <cstddef>
#include <math.h>

// Problem constants
#define NQ   2048
#define NS   65536
#define FD   512
#define KNN  16

// Tiling
#define BQ   128
#define BS   128
#define KC   32                  // fp32 K per chunk (4 x k8 mma steps)
#define NCH  (FD / KC)           // 16 chunks
#define SPLITS 9
#define SPS   7296               // 57 * 128
#define TPS   57
#define RS    36                 // smem row stride: {4g+tig} distinct mod 32
#define AS    (128 * RS)         // 4608 floats per operand tile
#define SDS   130                // dist tile stride
#define NCAND 32                 // rescored candidates per query

typedef unsigned long long ull;
typedef uint32_t u32;

// ---------------- scratch ---------------------------------------------------
__device__ float g_q2[NQ];
__device__ float g_s2[NS];
__device__ float g_pd[NQ * SPLITS * 32];
__device__ int   g_pi[NQ * SPLITS * 32];

// ---------------- helpers ---------------------------------------------------
__device__ __forceinline__ float tf32r(float x) {
    u32 r; asm("cvt.rna.tf32.f32 %0, %1;" : "=r"(r) : "f"(x));
    return __uint_as_float(r);
}
__device__ __forceinline__ float4 tf32r4(float4 v) {
    float4 o; o.x = tf32r(v.x); o.y = tf32r(v.y); o.z = tf32r(v.z); o.w = tf32r(v.w);
    return o;
}
// m16n8k8 tf32 mma (base PTX ISA path, valid on compute_103)
__device__ __forceinline__ void mma8(float (&c)[4], u32 a0, u32 a1, u32 a2, u32 a3,
                                     u32 b0, u32 b1) {
    asm volatile(
        "mma.sync.aligned.m16n8k8.row.col.f32.tf32.tf32.f32 "
        "{%0,%1,%2,%3}, {%4,%5,%6,%7}, {%8,%9}, {%0,%1,%2,%3};"
        : "+f"(c[0]), "+f"(c[1]), "+f"(c[2]), "+f"(c[3])
        : "r"(a0), "r"(a1), "r"(a2), "r"(a3), "r"(b0), "r"(b1));
}

__device__ __forceinline__ bool better(float d1, int i1, float d2, int i2) {
    return d1 < d2 || (d1 == d2 && i1 < i2);
}
__device__ __forceinline__ void insert16(float (&kd)[KNN], int (&ki)[KNN], float d, int i) {
    float cd = d; int ci = i;
#pragma unroll
    for (int j = 0; j < KNN; ++j) {
        bool b = better(cd, ci, kd[j], ki[j]);
        float td = kd[j]; int ti = ki[j];
        if (b) { kd[j] = cd; ki[j] = ci; cd = td; ci = ti; }
    }
}

// ---------------- kernel 0: row norms (bit-identical to the passing R3) -----
__global__ void knn_norms_kernel(const float* __restrict__ x, int nrows, int which) {
    int w    = (blockIdx.x * blockDim.x + threadIdx.x) >> 5;
    int lane = threadIdx.x & 31;
    if (w >= nrows) return;
    const float4* row = reinterpret_cast<const float4*>(x + (size_t)w * FD);
    float s = 0.f;
#pragma unroll
    for (int i = 0; i < FD / 4 / 32; ++i) {
        float4 v = row[lane + i * 32];
        s += v.x * v.x + v.y * v.y + v.z * v.z + v.w * v.w;
    }
#pragma unroll
    for (int o = 16; o > 0; o >>= 1) s += __shfl_xor_sync(0xffffffffu, s, o);
    if (lane == 0) { if (which) g_s2[w] = s; else g_q2[w] = s; }
}

// ---------------- kernel 1: 1-pass TF32 mma.sync GEMM (candidate filter) ----
// smem floats: [2 buf][A(AS), B(AS)] | sd(128*SDS) | q2s(128) | s2s(128)
#define SMEM_FLOATS (4 * AS + BQ * SDS + BQ + BS)

__global__ __launch_bounds__(256, 1)
void knn_mma_kernel(const float* __restrict__ Q, const float* __restrict__ S) {
    extern __shared__ float smem[];
    float* sd  = smem + 4 * AS;
    float* q2s = sd + BQ * SDS;
    float* s2s = q2s + BQ;

    const int tid  = threadIdx.x;
    const int wid  = tid >> 5, lane = tid & 31;
    const int wm   = wid >> 2, wn = wid & 3;        // 2x4 warp grid (64x32 warp tile)
    const int g    = lane >> 2, tig = lane & 3;
    const int qb   = blockIdx.x, sb = blockIdx.y;
    const int q0   = qb * BQ;
    const int sBase = sb * SPS;

    if (tid < BQ) q2s[tid] = g_q2[q0 + tid];

    // staging geometry: 4 float4 per thread per operand per chunk (KC=32)
    int rowv[4], kgv[4];
#pragma unroll
    for (int i = 0; i < 4; ++i) {
        int idx = tid + i * 256;       // 0..1023
        rowv[i] = idx >> 3;            // 0..127
        kgv[i]  = (idx & 7) * 4;       // 0..28
    }

    float kd[KNN]; int ki[KNN];
#pragma unroll
    for (int j = 0; j < KNN; ++j) { kd[j] = __int_as_float(0x7f800000); ki[j] = 0x7fffffff; }

    const int qrow = tid >> 1, hh = tid & 1;   // top-k scan roles

    // ---- preload tile 0, chunk 0 into buffer 0 ----
    {
        float* bA = smem;
        float* bB = smem + AS;
#pragma unroll
        for (int i = 0; i < 4; ++i) {
            float4 a = *(const float4*)(Q + (size_t)(q0 + rowv[i]) * FD + kgv[i]);
            float4 b = *(const float4*)(S + (size_t)(sBase + rowv[i]) * FD + kgv[i]);
            int so = rowv[i] * RS + kgv[i];
            *(float4*)(bA + so) = tf32r4(a);
            *(float4*)(bB + so) = tf32r4(b);
        }
    }
    __syncthreads();

    int buf = 0;

    for (int t = 0; t < TPS; ++t) {
        const int s0 = sBase + t * BS;
        if (s0 >= NS) break;
        if (tid < BS) s2s[tid] = g_s2[s0 + tid];

        float acc[4][4][4];
#pragma unroll
        for (int mt = 0; mt < 4; ++mt)
#pragma unroll
            for (int nt = 0; nt < 4; ++nt)
#pragma unroll
                for (int r = 0; r < 4; ++r) acc[mt][nt][r] = 0.f;

        for (int c = 0; c < NCH; ++c) {
            const bool hasNext = (c < NCH - 1) || ((t + 1 < TPS) && (s0 + BS < NS));
            int ccn, s0n;
            if (c < NCH - 1) { ccn = (c + 1) * KC; s0n = s0; }
            else             { ccn = 0;            s0n = s0 + BS; }

            float4 ra[4], rb[4];
            if (hasNext) {
#pragma unroll
                for (int i = 0; i < 4; ++i) {
                    ra[i] = *(const float4*)(Q + (size_t)(q0 + rowv[i]) * FD + ccn + kgv[i]);
                    rb[i] = *(const float4*)(S + (size_t)(s0n + rowv[i]) * FD + ccn + kgv[i]);
                }
            }

            // ---- consume current buffer: 4 k8 steps, 16 mma each ----
            {
                const float* bb = smem + buf * 2 * AS;
                const u32* uA = (const u32*)(bb)      + (wm * 64) * RS;
                const u32* uB = (const u32*)(bb + AS) + (wn * 32) * RS;
#pragma unroll
                for (int ks = 0; ks < 4; ++ks) {
                    const int kb = ks * 8 + tig;
                    u32 bf[4][2];
#pragma unroll
                    for (int nt = 0; nt < 4; ++nt) {
                        int ba = (nt * 8 + g) * RS + kb;
                        bf[nt][0] = uB[ba]; bf[nt][1] = uB[ba + 4];
                    }
#pragma unroll
                    for (int mt = 0; mt < 4; ++mt) {
                        int aa = (mt * 16 + g) * RS + kb;
                        u32 a0 = uA[aa],     a1 = uA[aa + 8 * RS];
                        u32 a2 = uA[aa + 4], a3 = uA[aa + 8 * RS + 4];
#pragma unroll
                        for (int nt = 0; nt < 4; ++nt)
                            mma8(acc[mt][nt], a0, a1, a2, a3, bf[nt][0], bf[nt][1]);
                    }
                }
            }

            // ---- stage next chunk into the other buffer ----
            if (hasNext) {
                float* dA = smem + (buf ^ 1) * 2 * AS;
                float* dB = dA + AS;
#pragma unroll
                for (int i = 0; i < 4; ++i) {
                    int so = rowv[i] * RS + kgv[i];
                    *(float4*)(dA + so) = tf32r4(ra[i]);
                    *(float4*)(dB + so) = tf32r4(rb[i]);
                }
            }
            __syncthreads();
            if (hasNext) buf ^= 1;
        }

        // ---- spill accumulators to dist tile ----
#pragma unroll
        for (int mt = 0; mt < 4; ++mt) {
            int row = wm * 64 + mt * 16 + g;
#pragma unroll
            for (int nt = 0; nt < 4; ++nt) {
                int col = wn * 32 + nt * 8 + 2 * tig;
                *(float2*)(sd + row * SDS + col)       = make_float2(acc[mt][nt][0], acc[mt][nt][1]);
                *(float2*)(sd + (row + 8) * SDS + col) = make_float2(acc[mt][nt][2], acc[mt][nt][3]);
            }
        }
        __syncthreads();

        // ---- approx top-16: 2 threads per query, 64 candidates each ----
        {
            const float  q2v  = q2s[qrow];
            const float* drow = sd + qrow * SDS + hh * 64;
            const float* s2p  = s2s + hh * 64;
#pragma unroll 8
            for (int j = 0; j < 64; ++j) {
                float d2 = fmaxf(q2v + s2p[j] - 2.f * drow[j], 1e-12f);
                int idx = s0 + hh * 64 + j;
                if (better(d2, idx, kd[KNN - 1], ki[KNN - 1])) insert16(kd, ki, d2, idx);
            }
        }
        __syncthreads();
    }

    // ---- emit per-(query, split) candidate lists ----
    {
        size_t b = ((size_t)(q0 + qrow) * SPLITS + sb) * 32 + (size_t)hh * 16;
#pragma unroll
        for (int r = 0; r < KNN; ++r) { g_pd[b + r] = kd[r]; g_pi[b + r] = ki[r]; }
    }
}

// ---------------- kernel 2: approx cut -> R3-exact fp32 rescore -------------
// Final ranking reproduces the (passing) R3 arithmetic bit-for-bit:
//   dot  = sequential fp32 FMA chain over k = 0..511 (ascending)
//   d2   = fmaxf(q2 + s2 - 2.f*dot, 1e-12f), q2/s2 from knn_norms_kernel
//   comparator (d2, idx) ascending
__global__ void knn_merge_kernel(const float* __restrict__ Q,
                                 const float* __restrict__ S,
                                 float* __restrict__ out) {
    int gw   = (blockIdx.x * blockDim.x + threadIdx.x) >> 5;  // query id
    int lane = threadIdx.x & 31;
    if (gw >= NQ) return;
    const float* pd = g_pd + (size_t)gw * (SPLITS * 32);
    const int*   pi = g_pi + (size_t)gw * (SPLITS * 32);

    // 288 approx candidates -> packed (d2_bits<<32)|idx, unique by idx
    ull key[9];
#pragma unroll
    for (int j = 0; j < 9; ++j) {
        int c = lane + j * 32;
        key[j] = ((ull)__float_as_uint(pd[c]) << 32) | (u32)pi[c];
    }
    // local ascending sort of 9 (odd-even)
#pragma unroll
    for (int p = 0; p < 9; ++p)
#pragma unroll
        for (int a = (p & 1); a + 1 < 9; a += 2)
            if (key[a + 1] < key[a]) { ull tk = key[a]; key[a] = key[a + 1]; key[a + 1] = tk; }

    // extract approx top-32; lane r keeps candidate r
    u32 myidx = 0u;
#pragma unroll
    for (int r = 0; r < NCAND; ++r) {
        ull m = key[0];
#pragma unroll
        for (int o = 16; o; o >>= 1) {
            ull v = __shfl_xor_sync(0xffffffffu, m, o);
            if (v < m) m = v;
        }
        if (key[0] == m) {                 // unique winner shifts its list
#pragma unroll
            for (int a = 0; a < 8; ++a) key[a] = key[a + 1];
            key[8] = ~0ull;
        }
        if (lane == r) myidx = (u32)m;
    }

    // ---- rescore: one candidate per lane, sequential fp32 FMA over k ----
    const float* qp = Q + (size_t)gw * FD;
    const float* sp = S + (size_t)myidx * FD;
    float dot = 0.f;
#pragma unroll 4
    for (int k = 0; k < FD; k += 4) {
        float4 qv = *(const float4*)(qp + k);
        float4 sv = *(const float4*)(sp + k);
        dot = fmaf(qv.x, sv.x, dot);
        dot = fmaf(qv.y, sv.y, dot);
        dot = fmaf(qv.z, sv.z, dot);
        dot = fmaf(qv.w, sv.w, dot);
    }
    const float q2v = g_q2[gw];
    const float s2v = g_s2[myidx];
    float d2 = fmaxf(q2v + s2v - 2.f * dot, 1e-12f);

    // ---- exact top-16 of the 32 by (d2, idx) ----
    ull k2 = ((ull)__float_as_uint(d2) << 32) | myidx;
    float find = 0.f; u32 fini = 0u;
#pragma unroll
    for (int r = 0; r < KNN; ++r) {
        ull m = k2;
#pragma unroll
        for (int o = 16; o; o >>= 1) {
            ull v = __shfl_xor_sync(0xffffffffu, m, o);
            if (v < m) m = v;
        }
        if (k2 == m) k2 = ~0ull;           // remove winner
        if (lane == r) { find = __uint_as_float((u32)(m >> 32)); fini = (u32)m; }
    }

    // ---- weights (same formula/precision as R3) ----
    float dist = sqrtf(find);              // find already clamped at 1e-12
    float sim  = (lane < KNN) ? 1.f / (dist + 1e-6f) : 0.f;
    float s = sim;
#pragma unroll
    for (int o = 16; o; o >>= 1) s += __shfl_xor_sync(0xffffffffu, s, o);
    if (lane < KNN) {
        out[(size_t)gw * KNN + lane] = (float)fini;
        out[(size_t)NQ * KNN + (size_t)gw * KNN + lane] = sim / s;
    }
}

// ---------------- launch ------------------------------------------------------
extern "C" void kernel_launch(void* const* d_in, const int* in_sizes, int n_in,
                              void* d_out, int out_size) {
    (void)in_sizes; (void)n_in; (void)out_size;
    const float* Q = (const float*)d_in[0];
    const float* S = (const float*)d_in[1];
    float* out = (float*)d_out;

    const int smem_bytes = SMEM_FLOATS * 4;   // ~138 KB
    cudaFuncSetAttribute(knn_mma_kernel,
                         cudaFuncAttributeMaxDynamicSharedMemorySize, smem_bytes);

    knn_norms_kernel<<<(NQ * 32) / 256, 256>>>(Q, NQ, 0);
    knn_norms_kernel<<<(NS * 32) / 256, 256>>>(S, NS, 1);

    dim3 grid(NQ / BQ, SPLITS);
    knn_mma_kernel<<<grid, 256, smem_bytes>>>(Q, S);

    knn_merge_kernel<<<NQ / 8, 256>>>(Q, S, out);
}